// round 8
// baseline (speedup 1.0000x reference)
#include <cuda_runtime.h>
#include <math.h>
#include <cstdint>

// Problem constants (fixed by the dataset)
#define L_DIM 16384
#define H_DIM 1024

// Tiling (same as R4/R7 best): block = CHUNK=64 rows x 256 channels,
// TPB=128, 2 channels/thread (float2). K=32 halo (threshold 2e-3; error
// scales as A^K -> ~2e-4, 5x under the 1e-3 tolerance). Traffic: 160 MB L2.
//
// R8 change: register double-buffer (prefetch depth = 8 rows, ~1/6 of DRAM
// latency -> issue stalls, measured issue=12.9%) replaced by a cp.async SMEM
// ring: 5 stages x 8 rows x 8KB = 40KB/block, prefetch depth 32-40 rows.
// Each thread copies and consumes ITS OWN smem lanes, so the steady-state
// loop needs no __syncthreads at all (wait_group only).
#define CHUNK  64
#define GROUPS 4          // H / 256
#define TPB    128
#define SROWS  8          // rows per pipeline stage
#define STAGES 5          // ring depth; 5*8KB = 40KB smem -> 5 blocks/SM

__device__ __forceinline__ void cpa8(uint32_t saddr, const float* gaddr) {
    asm volatile("cp.async.ca.shared.global [%0], [%1], 8;\n"
                 :: "r"(saddr), "l"(gaddr));
}
__device__ __forceinline__ void cpa_commit() {
    asm volatile("cp.async.commit_group;\n");
}
__device__ __forceinline__ void cpa_wait() {
    asm volatile("cp.async.wait_group %0;\n" :: "n"(STAGES - 1));
}

__global__ __launch_bounds__(TPB, 5)
void LI_scan_kernel(const float* __restrict__ x,
                    const float* __restrict__ tau,
                    float* __restrict__ out) {
    __shared__ float2 st[STAGES][SROWS][TPB];   // 40 KB

    const int tid         = threadIdx.x;
    const int chunk_start = blockIdx.x * CHUNK;
    const int ch          = (blockIdx.y * TPB + tid) * 2;

    // Per-channel decay A = exp(tau)
    float2 t = *reinterpret_cast<const float2*>(tau + ch);
    float2 A;
    A.x = expf(t.x); A.y = expf(t.y);

    // Runtime halo length K: smallest K with Amax^K < 2e-3 (measured error at
    // threshold 2e-4 was 2.2e-5; scales linearly with threshold -> ~2e-4 here,
    // 5x under the 1e-3 tolerance). Rounded to a stage multiple.
    float amax = fmaxf(A.x, A.y);
    int K;
    if (!(amax < 0.999999f)) {
        K = chunk_start;                       // no usable decay: exact prefix
    } else if (amax <= 1e-12f) {
        K = 0;
    } else {
        int ki = (int)ceilf(logf(2e-3f) / logf(amax));
        if (ki < 0) ki = 0;
        ki = (ki + SROWS - 1) & ~(SROWS - 1);  // round up to stage multiple
        K = ki < chunk_start ? ki : chunk_start;  // chunk_start % SROWS == 0
    }

    // Block-uniform K (uniform pipeline structure across the block)
    __shared__ int sK;
    if (tid == 0) sK = 0;
    __syncthreads();
    atomicMax(&sK, K);
    __syncthreads();
    K = sK;

    const float* px = x + ch;
    float*       po = out + ch;

    const int row0 = chunk_start - K;          // row of stage 0
    const int NS   = (K + CHUNK) / SROWS;      // total stages >= 8 > STAGES

    const uint32_t sbase =
        (uint32_t)__cvta_generic_to_shared(&st[0][0][0]) + tid * 8u;

    // ---- Prologue: fill the ring ----
    int issued = 0;
    for (; issued < STAGES; ++issued) {        // NS >= CHUNK/SROWS = 8 > STAGES
        const float*   g  = px + (row0 + issued * SROWS) * H_DIM;
        const uint32_t sa = sbase + (uint32_t)(issued % STAGES) * (SROWS * TPB * 8);
        #pragma unroll
        for (int j = 0; j < SROWS; ++j)
            cpa8(sa + j * (TPB * 8), g + j * H_DIM);
        cpa_commit();
    }

    // ---- Steady loop: wait oldest stage, consume, refill its slot ----
    float2 acc = make_float2(0.f, 0.f);
    for (int i = 0; i < NS; ++i) {
        cpa_wait();                            // groups 0..i complete
        const int  slot   = i % STAGES;
        const int  row    = row0 + i * SROWS;
        const bool storeQ = (row >= chunk_start);   // stage is all-halo or all-main

        #pragma unroll
        for (int j = 0; j < SROWS; ++j) {
            float2 v = st[slot][j][tid];       // own lanes: no __syncthreads needed
            acc.x = fmaf(A.x, acc.x, v.x);
            acc.y = fmaf(A.y, acc.y, v.y);
            if (storeQ)                        // evict-first: protect x[] in L2
                __stcs(reinterpret_cast<float2*>(po + (row + j) * H_DIM), acc);
        }

        if (issued < NS) {                     // refill the slot just consumed
            const float*   g  = px + (row0 + issued * SROWS) * H_DIM;
            const uint32_t sa = sbase + (uint32_t)(issued % STAGES) * (SROWS * TPB * 8);
            #pragma unroll
            for (int j = 0; j < SROWS; ++j)
                cpa8(sa + j * (TPB * 8), g + j * H_DIM);
            cpa_commit();
            ++issued;
        } else {
            cpa_commit();                      // empty group keeps wait accounting exact
            ++issued;
        }
    }
}

extern "C" void kernel_launch(void* const* d_in, const int* in_sizes, int n_in,
                              void* d_out, int out_size) {
    const float* x   = (const float*)d_in[0];   // (L, H) fp32
    const float* tau = (const float*)d_in[1];   // (H,)   fp32
    float*       out = (float*)d_out;           // (L, H) fp32

    dim3 grid(L_DIM / CHUNK, GROUPS);           // (256, 4) = 1024 blocks
    LI_scan_kernel<<<grid, TPB>>>(x, tau, out);
}

// round 9
// speedup vs baseline: 1.1469x; 1.1469x over previous
#include <cuda_runtime.h>
#include <math.h>

// Problem constants (fixed by the dataset)
#define L_DIM 16384
#define H_DIM 1024

// R9: scalar (1 channel/thread) + 4-deep register pipeline.
//   block = CHUNK=64 rows x 128 channels, TPB=128, GROUPS=8 -> grid 2048
//   blocks = 8192 warps (~32 warps/SM at 8 blocks/SM = occ ~50%).
//   Scalar buffers are 8 regs each -> 4 rotating buffers (prefetch depth
//   24 rows ~ 3x R7) fit the 64-reg budget that 8 blocks/SM requires.
//   Traffic (160 MB), halo K=40, and 104-row serial chain all unchanged
//   from R7 -- this round buys pure latency coverage.
#define CHUNK  64
#define GROUPS 8          // H / TPB
#define TPB    128
#define BATCH  8          // rows per buffer
#define OHD    (BATCH * H_DIM)

__device__ __forceinline__ void loadB(float v[BATCH], const float* px, int off) {
#pragma unroll
    for (int j = 0; j < BATCH; ++j)
        v[j] = px[off + j * H_DIM];     // 8 back-to-back LDG.32 (128B/warp coalesced)
}

__device__ __forceinline__ void procB(const float v[BATCH], float A, float& acc,
                                      float* po, int off, bool store) {
#pragma unroll
    for (int j = 0; j < BATCH; ++j) {
        acc = fmaf(A, acc, v[j]);
        if (store)   // evict-first store: don't let out[] evict x[] halo lines from L2
            __stcs(po + off + j * H_DIM, acc);
    }
}

// 8 blocks/SM (1024 threads) -> 64-reg/thread budget; 4 buffers take 32.
__global__ __launch_bounds__(TPB, 8)
void LI_scan_kernel(const float* __restrict__ x,
                    const float* __restrict__ tau,
                    float* __restrict__ out) {
    const int chunk_start = blockIdx.x * CHUNK;
    const int ch          = blockIdx.y * TPB + threadIdx.x;

    // Per-channel decay A = exp(tau)
    const float A = expf(tau[ch]);

    // Runtime halo length K: smallest K with A^K < 2e-4 (measured rel_err at
    // this threshold: 2.2e-5, 45x under the 1e-3 tolerance). Rounded up to a
    // BATCH multiple. Falls back to exact full prefix if A ~ 1.
    int K;
    if (!(A < 0.999999f)) {
        K = chunk_start;                       // no usable decay: exact prefix
    } else if (A <= 1e-12f) {
        K = 0;
    } else {
        int ki = (int)ceilf(logf(2e-4f) / logf(A));
        if (ki < 0) ki = 0;
        ki = (ki + BATCH - 1) & ~(BATCH - 1);  // round up to multiple of BATCH
        K = ki < chunk_start ? ki : chunk_start;  // chunk_start % BATCH == 0
    }

    // Block-uniform K (keeps pipeline structure aligned across the block)
    __shared__ int sK;
    if (threadIdx.x == 0) sK = 0;
    __syncthreads();
    atomicMax(&sK, K);
    __syncthreads();
    K = sK;

    const float* px = x + ch;
    float*       po = out + ch;

    float acc = 0.f;

    // ---- Fused halo + main loop, 4-deep software pipeline ----
    // Rows [chunk_start-K, chunk_start) warm up acc (no stores);
    // rows [chunk_start, chunk_start+CHUNK) also store. K and CHUNK are
    // multiples of BATCH, so each batch is uniformly halo or main.
    // 32-bit element offsets: L*H = 2^24 fits comfortably.
    int off        = (chunk_start - K) * H_DIM;  // current batch offset
    const int off0 = chunk_start * H_DIM;        // first storing offset
    const int nb   = (K + CHUNK) / BATCH;        // >= CHUNK/BATCH = 8

    float v0[BATCH], v1[BATCH], v2[BATCH], v3[BATCH];
    loadB(v0, px, off);
    if (nb > 1) loadB(v1, px, off + OHD);
    if (nb > 2) loadB(v2, px, off + 2 * OHD);
    int b = 0;
    while (true) {
        if (b + 3 < nb) loadB(v3, px, off + 3 * OHD);   // prefetch 3 batches ahead
        procB(v0, A, acc, po, off, off >= off0);
        off += OHD; if (++b >= nb) break;
        if (b + 3 < nb) loadB(v0, px, off + 3 * OHD);
        procB(v1, A, acc, po, off, off >= off0);
        off += OHD; if (++b >= nb) break;
        if (b + 3 < nb) loadB(v1, px, off + 3 * OHD);
        procB(v2, A, acc, po, off, off >= off0);
        off += OHD; if (++b >= nb) break;
        if (b + 3 < nb) loadB(v2, px, off + 3 * OHD);
        procB(v3, A, acc, po, off, off >= off0);
        off += OHD; if (++b >= nb) break;
    }
}

extern "C" void kernel_launch(void* const* d_in, const int* in_sizes, int n_in,
                              void* d_out, int out_size) {
    const float* x   = (const float*)d_in[0];   // (L, H) fp32
    const float* tau = (const float*)d_in[1];   // (H,)   fp32
    float*       out = (float*)d_out;           // (L, H) fp32

    dim3 grid(L_DIM / CHUNK, GROUPS);           // (256, 8) = 2048 blocks
    LI_scan_kernel<<<grid, TPB>>>(x, tau, out);
}